// round 4
// baseline (speedup 1.0000x reference)
#include <cuda_runtime.h>
#include <cuda_bf16.h>

// Problem constants (fixed by setup_inputs)
constexpr int N  = 8;
constexpr int C  = 256;
constexpr int H  = 160;
constexpr int W  = 160;
constexpr int OH = 14;
constexpr int OW = 14;
constexpr float SCALE_H = 160.0f;
constexpr float SCALE_W = 160.0f;
constexpr int HW = H * W;          // 25600
constexpr int C4 = C / 4;          // 64
constexpr int PAIR_MAXB = 640;     // per-pair roi bound (mean 256, +25 sigma)

// L2-resident NHWC scratch for TWO images: 2 * 26.2 MB = 52.4 MB
__device__ float g_scr[2][(size_t)HW * C];
// batch-sorted roi processing order + batch segment offsets
__device__ int   g_order[2048];
__device__ int   g_base[N + 1];

// ---------------------------------------------------------------------------
// Kernel 0: counting-sort roi indices by batch id. Single block.
// Order within a batch is nondeterministic, but every consumer block writes
// only its own out[k] slice, so d_out is fully deterministic.
// ---------------------------------------------------------------------------
__global__ void sort_rois_kernel(const float* __restrict__ rois, int K) {
    __shared__ int cnt[N];
    __shared__ int base[N];
    const int t = threadIdx.x;
    if (t < N) cnt[t] = 0;
    __syncthreads();
    int b = 0;
    if (t < K) {
        b = (int)rois[t * 5];
        atomicAdd(&cnt[b], 1);
    }
    __syncthreads();
    if (t == 0) {
        int s = 0;
        for (int i = 0; i < N; i++) { base[i] = s; g_base[i] = s; s += cnt[i]; }
        g_base[N] = s;
    }
    __syncthreads();
    if (t < K) {
        int pos = atomicAdd(&base[b], 1);
        g_order[pos] = t;
    }
}

// ---------------------------------------------------------------------------
// Kernel 1: per-pair NCHW -> NHWC transpose into L2-resident scratch.
// blockIdx.z in {0,1} selects batch n0+z -> scratch half z.
// 32(c) x 32(hw) float tile, block (8,32), float4 both sides, pitch 33.
// ---------------------------------------------------------------------------
__global__ __launch_bounds__(256)
void transpose_phase_kernel(const float* __restrict__ feat, int n0) {
    __shared__ float s[32][33];
    const int z   = blockIdx.z;          // 0..1
    const int n   = n0 + z;
    const int hw0 = blockIdx.x * 32;
    const int c0  = blockIdx.y * 32;
    const int tx  = threadIdx.x;         // 0..7  (float4 lane)
    const int ty  = threadIdx.y;         // 0..31

    const float4* src4 = (const float4*)(feat + (size_t)n * C * HW);
    float4 v = __ldcs(&src4[(size_t)(c0 + ty) * (HW / 4) + (hw0 >> 2) + tx]);
    s[ty][tx * 4 + 0] = v.x;
    s[ty][tx * 4 + 1] = v.y;
    s[ty][tx * 4 + 2] = v.z;
    s[ty][tx * 4 + 3] = v.w;
    __syncthreads();

    float4 w;
    w.x = s[tx * 4 + 0][ty];
    w.y = s[tx * 4 + 1][ty];
    w.z = s[tx * 4 + 2][ty];
    w.w = s[tx * 4 + 3][ty];
    float4* dst4 = (float4*)g_scr[z];
    dst4[(size_t)(hw0 + ty) * C4 + (c0 >> 2) + tx] = w;
}

// ---------------------------------------------------------------------------
// Kernel 2: RoI Align phase for batch pair `pair` (batches 2p, 2p+1).
// Grid: PAIR_MAXB * OH blocks; blocks beyond the pair's roi count exit.
// 256 threads = 64 channel-quads x 4 ox-groups, float4 corner gathers from
// the L2-resident scratch half selected by batch parity. Results staged in
// smem, flushed linearized with streaming stores.
// ---------------------------------------------------------------------------
__global__ __launch_bounds__(256)
void roialign_phase_kernel(const float* __restrict__ rois,
                           float* __restrict__ out, int pair) {
    const int r   = blockIdx.x / OH;     // roi slot within pair
    const int oy  = blockIdx.x % OH;
    const int j   = g_base[2 * pair] + r;       // sorted position
    if (j >= g_base[2 * pair + 2]) return;
    const int tid = threadIdx.x;
    const int c4  = tid & 63;            // channel quad 0..63
    const int oxg = tid >> 6;            // ox group 0..3
    const int k   = g_order[j];

    __shared__ float s_roi[5];
    __shared__ int   s_o0[OW], s_o1[OW];
    __shared__ float s_w00[OW], s_w01[OW], s_w10[OW], s_w11[OW];
    __shared__ int   s_row0, s_row1;
    __shared__ float4 s_tile4[OW][C4 + 1];   // [ox][c4], pitch 65 float4

    if (tid < 5) s_roi[tid] = rois[k * 5 + tid];
    __syncthreads();

    if (tid < OW) {
        const int ox = tid;
        const float px1 = s_roi[1] * SCALE_W;
        const float py1 = s_roi[2] * SCALE_H;
        const float px2 = s_roi[3] * SCALE_W;
        const float py2 = s_roi[4] * SCALE_H;

        const float gx = (float)ox * (1.0f / (float)(OW - 1));
        const float gy = (float)oy * (1.0f / (float)(OH - 1));
        const float fx = px1 + gx * (px2 - px1);
        const float fy = py1 + gy * (py2 - py1);

        // mirror the reference's (unaligned) coordinate math exactly
        const float ngx = fx / (float)W * 2.0f - 1.0f;
        const float ngy = fy / (float)H * 2.0f - 1.0f;
        const float ix  = ((ngx + 1.0f) * (float)W - 1.0f) * 0.5f;
        const float iy  = ((ngy + 1.0f) * (float)H - 1.0f) * 0.5f;

        const int x0  = (int)floorf(ix);
        const int y0  = (int)floorf(iy);
        const int x1i = x0 + 1;
        const int y1i = y0 + 1;

        const float wx1 = ix - (float)x0;
        const float wx0 = 1.0f - wx1;
        const float wy1 = iy - (float)y0;
        const float wy0 = 1.0f - wy1;

        const float vx0 = (x0  >= 0 && x0  < W) ? 1.0f : 0.0f;
        const float vx1 = (x1i >= 0 && x1i < W) ? 1.0f : 0.0f;
        const float vy0 = (y0  >= 0 && y0  < H) ? 1.0f : 0.0f;
        const float vy1 = (y1i >= 0 && y1i < H) ? 1.0f : 0.0f;

        const int x0c = min(max(x0,  0), W - 1);
        const int x1c = min(max(x1i, 0), W - 1);

        s_o0[ox]  = x0c * C4;            // x offset in float4 units
        s_o1[ox]  = x1c * C4;
        s_w00[ox] = wy0 * wx0 * vy0 * vx0;
        s_w01[ox] = wy0 * wx1 * vy0 * vx1;
        s_w10[ox] = wy1 * wx0 * vy1 * vx0;
        s_w11[ox] = wy1 * wx1 * vy1 * vx1;

        if (ox == 0) {
            const int y0c = min(max(y0,  0), H - 1);
            const int y1c = min(max(y1i, 0), H - 1);
            s_row0 = y0c * W * C4;       // row offset in float4 units
            s_row1 = y1c * W * C4;
        }
    }
    __syncthreads();

    const int half = ((int)s_roi[0]) & 1;     // batch parity -> scratch half
    const float4* __restrict__ f = (const float4*)g_scr[half];
    const int r0 = s_row0;
    const int r1 = s_row1;

    #pragma unroll
    for (int ox = oxg; ox < OW; ox += 4) {
        const int a0 = s_o0[ox] + c4;
        const int a1 = s_o1[ox] + c4;
        const float w00 = s_w00[ox];
        const float w01 = s_w01[ox];
        const float w10 = s_w10[ox];
        const float w11 = s_w11[ox];
        const float4 v00 = __ldg(&f[r0 + a0]);
        const float4 v01 = __ldg(&f[r0 + a1]);
        const float4 v10 = __ldg(&f[r1 + a0]);
        const float4 v11 = __ldg(&f[r1 + a1]);
        float4 rr;
        rr.x = v00.x * w00 + v01.x * w01 + v10.x * w10 + v11.x * w11;
        rr.y = v00.y * w00 + v01.y * w01 + v10.y * w10 + v11.y * w11;
        rr.z = v00.z * w00 + v01.z * w01 + v10.z * w10 + v11.z * w11;
        rr.w = v00.w * w00 + v01.w * w01 + v10.w * w10 + v11.w * w11;
        s_tile4[ox][c4] = rr;
    }
    __syncthreads();

    // Linearized flush with streaming stores (protect scratch L2 residency)
    const float* s_t = (const float*)s_tile4;
    float* __restrict__ outk = out + (size_t)k * C * OH * OW + oy * OW;
    constexpr int TOTAL = C * OW;        // 3584
    constexpr int PITCH = (C4 + 1) * 4;  // 260
    for (int jj = tid; jj < TOTAL; jj += 256) {
        const int cc = jj / OW;
        const int ox = jj - cc * OW;
        __stcs(&outk[cc * (OH * OW) + ox], s_t[ox * PITCH + cc]);
    }
}

// ---------------------------------------------------------------------------
// Kernel 3: safety tail. Handles any roi whose within-pair rank exceeded
// PAIR_MAXB (statistically never). Direct-NCHW slow path, thread = channel.
// ---------------------------------------------------------------------------
__global__ __launch_bounds__(256)
void roialign_tail_kernel(const float* __restrict__ feat,
                          const float* __restrict__ rois,
                          float* __restrict__ out) {
    const int j  = blockIdx.x / OH;      // sorted position
    const int oy = blockIdx.x % OH;
    const int k  = g_order[j];
    const int b  = (int)rois[k * 5];
    if (j - g_base[b & ~1] < PAIR_MAXB) return;   // already handled by a phase

    const int c = threadIdx.x;
    const float px1 = rois[k * 5 + 1] * SCALE_W;
    const float py1 = rois[k * 5 + 2] * SCALE_H;
    const float px2 = rois[k * 5 + 3] * SCALE_W;
    const float py2 = rois[k * 5 + 4] * SCALE_H;
    const float gy = (float)oy * (1.0f / (float)(OH - 1));
    const float fy = py1 + gy * (py2 - py1);
    const float ngy = fy / (float)H * 2.0f - 1.0f;
    const float iy  = ((ngy + 1.0f) * (float)H - 1.0f) * 0.5f;
    const int y0  = (int)floorf(iy);
    const int y1i = y0 + 1;
    const float wy1 = iy - (float)y0;
    const float wy0 = 1.0f - wy1;
    const float vy0 = (y0  >= 0 && y0  < H) ? 1.0f : 0.0f;
    const float vy1 = (y1i >= 0 && y1i < H) ? 1.0f : 0.0f;
    const int y0c = min(max(y0,  0), H - 1);
    const int y1c = min(max(y1i, 0), H - 1);

    const float* fc = feat + ((size_t)b * C + c) * HW;
    float* outk = out + (size_t)k * C * OH * OW + (size_t)c * OH * OW + oy * OW;

    for (int ox = 0; ox < OW; ox++) {
        const float gx = (float)ox * (1.0f / (float)(OW - 1));
        const float fx = px1 + gx * (px2 - px1);
        const float ngx = fx / (float)W * 2.0f - 1.0f;
        const float ix  = ((ngx + 1.0f) * (float)W - 1.0f) * 0.5f;
        const int x0  = (int)floorf(ix);
        const int x1i = x0 + 1;
        const float wx1 = ix - (float)x0;
        const float wx0 = 1.0f - wx1;
        const float vx0 = (x0  >= 0 && x0  < W) ? 1.0f : 0.0f;
        const float vx1 = (x1i >= 0 && x1i < W) ? 1.0f : 0.0f;
        const int x0c = min(max(x0,  0), W - 1);
        const int x1c = min(max(x1i, 0), W - 1);
        const float v00 = fc[y0c * W + x0c];
        const float v01 = fc[y0c * W + x1c];
        const float v10 = fc[y1c * W + x0c];
        const float v11 = fc[y1c * W + x1c];
        outk[ox] = v00 * (wy0 * wx0 * vy0 * vx0)
                 + v01 * (wy0 * wx1 * vy0 * vx1)
                 + v10 * (wy1 * wx0 * vy1 * vx0)
                 + v11 * (wy1 * wx1 * vy1 * vx1);
    }
}

extern "C" void kernel_launch(void* const* d_in, const int* in_sizes, int n_in,
                              void* d_out, int out_size) {
    const float* feat = (const float*)d_in[0];
    const float* rois = (const float*)d_in[1];
    float* out = (float*)d_out;

    const int K = in_sizes[1] / 5;   // 1024

    // Kernel 0: batch-sort roi order
    sort_rois_kernel<<<1, 1024>>>(rois, K);

    // Phased: transpose a batch pair into L2-resident scratch, then consume it
    dim3 tgrid(HW / 32, C / 32, 2);  // (800, 8, 2)
    dim3 tblock(8, 32);
    for (int p = 0; p < N / 2; p++) {
        transpose_phase_kernel<<<tgrid, tblock>>>(feat, 2 * p);
        roialign_phase_kernel<<<PAIR_MAXB * OH, 256>>>(rois, out, p);
    }

    // Safety tail (normally exits immediately everywhere)
    roialign_tail_kernel<<<K * OH, 256>>>(feat, rois, out);
}